// round 6
// baseline (speedup 1.0000x reference)
#include <cuda_runtime.h>
#include <cuda_bf16.h>
#include <math.h>
#include <stdint.h>

// Problem constants
#define Bc   8
#define Sc   512
#define Dc   1024
#define Hc   16
#define DHc  64
#define Mc   1024
#define DFc  4096
#define Vc   32000
#define Lc   6

// ---------------------------------------------------------------------------
// Scratch (device globals: allocation-free per harness rules)
// ---------------------------------------------------------------------------
__device__ float g_x[Bc * Sc * Dc];
__device__ float g_q[Bc * Sc * Dc];
__device__ float g_k[Bc * Mc * Dc];
__device__ float g_v[Bc * Mc * Dc];
__device__ float g_a[Bc * Sc * Dc];
__device__ float g_o[Bc * Sc * Dc];
__device__ float g_f[Bc * Sc * DFc];

// Pre-converted weights: [N,K] bf16 hi/lo.
#define WOFF_LAYER 16777216ull
#define WOFF_W1    8388608ull
#define WOFF_W2    12582912ull
#define EOFF       100663296ull
#define WTOTAL     133431296ull
__device__ __nv_bfloat16 g_whi[WTOTAL];
__device__ __nv_bfloat16 g_wlo[WTOTAL];

// ===========================================================================
// helpers
// ===========================================================================
__device__ __forceinline__ uint32_t smem_u32(const void* p) {
    uint32_t a;
    asm("{ .reg .u64 t; cvta.to.shared.u64 t, %1; cvt.u32.u64 %0, t; }"
        : "=r"(a) : "l"(p));
    return a;
}

__device__ __forceinline__ void split2(float x, float y, uint32_t& hi, uint32_t& lo) {
    __nv_bfloat162 h = __floats2bfloat162_rn(x, y);
    float rx = x - __low2float(h);
    float ry = y - __high2float(h);
    __nv_bfloat162 l = __floats2bfloat162_rn(rx, ry);
    hi = *reinterpret_cast<uint32_t*>(&h);
    lo = *reinterpret_cast<uint32_t*>(&l);
}

__device__ __forceinline__ void mma_bf16(float* d, const uint32_t* a, const uint32_t* b) {
    asm volatile(
        "mma.sync.aligned.m16n8k16.row.col.f32.bf16.bf16.f32 "
        "{%0,%1,%2,%3}, {%4,%5,%6,%7}, {%8,%9}, {%0,%1,%2,%3};"
        : "+f"(d[0]), "+f"(d[1]), "+f"(d[2]), "+f"(d[3])
        : "r"(a[0]), "r"(a[1]), "r"(a[2]), "r"(a[3]), "r"(b[0]), "r"(b[1]));
}

#define CP_ASYNC16(dst, src) \
    asm volatile("cp.async.cg.shared.global [%0], [%1], 16;" :: "r"(dst), "l"(src))
#define CP_COMMIT()  asm volatile("cp.async.commit_group;" ::: "memory")
#define CP_WAIT0()   asm volatile("cp.async.wait_group 0;" ::: "memory")

// ===========================================================================
// Weight conversion kernels (4 launches total, batched)
// ===========================================================================
__global__ void convT8_kernel(const float* __restrict__ Wq, const float* __restrict__ Wk,
                              const float* __restrict__ Wv, const float* __restrict__ Wo,
                              const float* __restrict__ Wqc, const float* __restrict__ Wkc,
                              const float* __restrict__ Wvc, const float* __restrict__ Woc,
                              __nv_bfloat16* __restrict__ hi, __nv_bfloat16* __restrict__ lo)
{
    __shared__ float ts[32][33];
    const int z     = blockIdx.z;
    const int layer = z >> 3;
    const int j     = z & 7;
    const float* srcs[8] = { Wq, Wk, Wv, Wo, Wqc, Wkc, Wvc, Woc };
    const float* W = srcs[j] + (size_t)layer * Dc * Dc;
    __nv_bfloat16* ho  = hi + (size_t)layer * WOFF_LAYER + (size_t)j * 1048576;
    __nv_bfloat16* lo_ = lo + (size_t)layer * WOFF_LAYER + (size_t)j * 1048576;

    const int k0 = blockIdx.y * 32, n0 = blockIdx.x * 32;
    const int tx = threadIdx.x, ty = threadIdx.y;
#pragma unroll
    for (int jj = 0; jj < 4; jj++)
        ts[ty + jj * 8][tx] = W[(size_t)(k0 + ty + jj * 8) * Dc + n0 + tx];
    __syncthreads();
#pragma unroll
    for (int jj = 0; jj < 4; jj++) {
        int n = ty + jj * 8;
        float v = ts[tx][n];
        __nv_bfloat16 h = __float2bfloat16(v);
        float r = v - __bfloat162float(h);
        size_t o = (size_t)(n0 + n) * Dc + k0 + tx;
        ho[o]  = h;
        lo_[o] = __float2bfloat16(r);
    }
}

__global__ void convT_kernel(const float* __restrict__ W,
                             __nv_bfloat16* __restrict__ hi,
                             __nv_bfloat16* __restrict__ lo, int K, int N,
                             size_t srcStride, size_t dstStride)
{
    __shared__ float ts[32][33];
    const int z  = blockIdx.z;
    const float* Ws = W + (size_t)z * srcStride;
    __nv_bfloat16* ho  = hi + (size_t)z * dstStride;
    __nv_bfloat16* lo_ = lo + (size_t)z * dstStride;
    const int k0 = blockIdx.y * 32, n0 = blockIdx.x * 32;
    const int tx = threadIdx.x, ty = threadIdx.y;
#pragma unroll
    for (int j = 0; j < 4; j++)
        ts[ty + j * 8][tx] = Ws[(size_t)(k0 + ty + j * 8) * N + n0 + tx];
    __syncthreads();
#pragma unroll
    for (int j = 0; j < 4; j++) {
        int n = ty + j * 8;
        float v = ts[tx][n];
        __nv_bfloat16 h = __float2bfloat16(v);
        float r = v - __bfloat162float(h);
        size_t o = (size_t)(n0 + n) * K + k0 + tx;
        ho[o]  = h;
        lo_[o] = __float2bfloat16(r);
    }
}

__global__ void conv_kernel(const float4* __restrict__ src,
                            __nv_bfloat162* __restrict__ hi,
                            __nv_bfloat162* __restrict__ lo)
{
    size_t i = (size_t)blockIdx.x * blockDim.x + threadIdx.x;
    float4 v = src[i];
    __nv_bfloat162 h0 = __floats2bfloat162_rn(v.x, v.y);
    __nv_bfloat162 h1 = __floats2bfloat162_rn(v.z, v.w);
    float rx = v.x - __low2float(h0), ry = v.y - __high2float(h0);
    float rz = v.z - __low2float(h1), rw = v.w - __high2float(h1);
    hi[i * 2]     = h0;
    hi[i * 2 + 1] = h1;
    lo[i * 2]     = __floats2bfloat162_rn(rx, ry);
    lo[i * 2 + 1] = __floats2bfloat162_rn(rz, rw);
}

// ===========================================================================
// Tensor-core GEMM (R4-proven scalar-LDS fragment loads):
//   C[M,N] = A[M,K](fp32) @ Wt[N,K](bf16 hi/lo)  (+bias, +relu)
// 3-pass hi/lo split, fp32 accum. 128x128 CTA, BK=64, 8 warps (2x4), 64x32 warp.
// ===========================================================================
#define PITCH 72                          // bf16 elems per smem row (64 used)
#define TILEB (128 * PITCH * 2)           // 18432 B
#define STAGEB (4 * TILEB)                // 73728 B  (Ahi, Alo, Bhi, Blo)
#define GEMM_SMEM (2 * STAGEB)            // 147456 B

template <bool BIAS, bool RELU>
__global__ void __launch_bounds__(256, 1)
tc_gemm(const float* __restrict__ A,
        const __nv_bfloat16* __restrict__ Bhi_g,
        const __nv_bfloat16* __restrict__ Blo_g,
        const float* __restrict__ bias, float* __restrict__ C,
        int M, int N, int K)
{
    extern __shared__ char smem[];
    const int tid  = threadIdx.x;
    const int wid  = tid >> 5;
    const int lane = tid & 31;
    const int g    = lane >> 2;
    const int t    = lane & 3;
    const int wm   = wid & 1;
    const int wn   = wid >> 1;
    const int m0   = blockIdx.y * 128;
    const int n0   = blockIdx.x * 128;

    const int arow = tid >> 4;   // 0..15 (x8 iters -> 128 rows)
    const int ac4  = tid & 15;   // float4 index within 64-col row

    float4 aR[8];
    float acc[4][4][4];
#pragma unroll
    for (int i = 0; i < 4; i++)
#pragma unroll
        for (int j = 0; j < 4; j++)
#pragma unroll
            for (int c = 0; c < 4; c++) acc[i][j][c] = 0.f;

    const int S = K >> 6;

    auto ldgA = [&](int s) {
        const int k0 = s << 6;
#pragma unroll
        for (int i = 0; i < 8; i++) {
            int row = arow + i * 16;
            aR[i] = *reinterpret_cast<const float4*>(
                A + (size_t)(m0 + row) * K + k0 + ac4 * 4);
        }
    };

    auto stsA = [&](int b) {
        char* Ahi = smem + b * STAGEB;
        char* Alo = Ahi + TILEB;
#pragma unroll
        for (int i = 0; i < 8; i++) {
            int row = arow + i * 16;
            uint32_t h0, l0, h1, l1;
            split2(aR[i].x, aR[i].y, h0, l0);
            split2(aR[i].z, aR[i].w, h1, l1);
            uint32_t byte = (uint32_t)(row * (PITCH * 2) + ac4 * 8);
            *reinterpret_cast<uint64_t*>(Ahi + byte) = ((uint64_t)h1 << 32) | h0;
            *reinterpret_cast<uint64_t*>(Alo + byte) = ((uint64_t)l1 << 32) | l0;
        }
    };

    auto cpB = [&](int s, int b) {
        const int k0 = s << 6;
        char* Bhi_s = smem + b * STAGEB + 2 * TILEB;
        char* Blo_s = smem + b * STAGEB + 3 * TILEB;
#pragma unroll
        for (int i = 0; i < 8; i++) {
            int idx  = tid + i * 256;
            int r    = (idx & 1023) >> 3;
            int c16  = idx & 7;
            uint32_t dst;
            const __nv_bfloat16* src;
            if (i < 4) {
                src = Bhi_g + (size_t)(n0 + r) * K + k0 + c16 * 8;
                dst = smem_u32(Bhi_s + r * (PITCH * 2) + c16 * 16);
            } else {
                src = Blo_g + (size_t)(n0 + r) * K + k0 + c16 * 8;
                dst = smem_u32(Blo_s + r * (PITCH * 2) + c16 * 16);
            }
            CP_ASYNC16(dst, src);
        }
    };

    auto compute = [&](int b) {
        const __nv_bfloat16* Ah = reinterpret_cast<const __nv_bfloat16*>(smem + b * STAGEB);
        const __nv_bfloat16* Al = Ah + 128 * PITCH;
        const __nv_bfloat16* Bh = Al + 128 * PITCH;
        const __nv_bfloat16* Bl = Bh + 128 * PITCH;
#pragma unroll
        for (int ks = 0; ks < 4; ks++) {
            const int kb = ks * 16 + t * 2;
            uint32_t ah[4][4], al[4][4], bh[4][2], bl[4][2];
#pragma unroll
            for (int mt = 0; mt < 4; mt++) {
                const __nv_bfloat16* p = Ah + (wm * 64 + mt * 16 + g) * PITCH + kb;
                ah[mt][0] = *reinterpret_cast<const uint32_t*>(p);
                ah[mt][1] = *reinterpret_cast<const uint32_t*>(p + 8 * PITCH);
                ah[mt][2] = *reinterpret_cast<const uint32_t*>(p + 8);
                ah[mt][3] = *reinterpret_cast<const uint32_t*>(p + 8 * PITCH + 8);
            }
#pragma unroll
            for (int nt = 0; nt < 4; nt++) {
                const __nv_bfloat16* p = Bh + (wn * 32 + nt * 8 + g) * PITCH + kb;
                bh[nt][0] = *reinterpret_cast<const uint32_t*>(p);
                bh[nt][1] = *reinterpret_cast<const uint32_t*>(p + 8);
            }
#pragma unroll
            for (int mt = 0; mt < 4; mt++)
#pragma unroll
                for (int nt = 0; nt < 4; nt++)
                    mma_bf16(acc[mt][nt], ah[mt], bh[nt]);
#pragma unroll
            for (int nt = 0; nt < 4; nt++) {
                const __nv_bfloat16* p = Bl + (wn * 32 + nt * 8 + g) * PITCH + kb;
                bl[nt][0] = *reinterpret_cast<const uint32_t*>(p);
                bl[nt][1] = *reinterpret_cast<const uint32_t*>(p + 8);
            }
#pragma unroll
            for (int mt = 0; mt < 4; mt++)
#pragma unroll
                for (int nt = 0; nt < 4; nt++)
                    mma_bf16(acc[mt][nt], ah[mt], bl[nt]);
#pragma unroll
            for (int mt = 0; mt < 4; mt++) {
                const __nv_bfloat16* p = Al + (wm * 64 + mt * 16 + g) * PITCH + kb;
                al[mt][0] = *reinterpret_cast<const uint32_t*>(p);
                al[mt][1] = *reinterpret_cast<const uint32_t*>(p + 8 * PITCH);
                al[mt][2] = *reinterpret_cast<const uint32_t*>(p + 8);
                al[mt][3] = *reinterpret_cast<const uint32_t*>(p + 8 * PITCH + 8);
            }
#pragma unroll
            for (int mt = 0; mt < 4; mt++)
#pragma unroll
                for (int nt = 0; nt < 4; nt++)
                    mma_bf16(acc[mt][nt], al[mt], bh[nt]);
        }
    };

    // ---- pipeline ----
    ldgA(0);
    cpB(0, 0);
    CP_COMMIT();
    stsA(0);
    CP_WAIT0();
    __syncthreads();

    for (int s = 0; s < S; s++) {
        const int b = s & 1;
        if (s + 1 < S) { ldgA(s + 1); cpB(s + 1, b ^ 1); CP_COMMIT(); }
        compute(b);
        if (s + 1 < S) stsA(b ^ 1);
        CP_WAIT0();
        __syncthreads();
    }

    // ---- epilogue ----
    float* stage = reinterpret_cast<float*>(smem);   // 128 x pitch 132
#pragma unroll
    for (int mt = 0; mt < 4; mt++) {
#pragma unroll
        for (int nt = 0; nt < 4; nt++) {
            int row = wm * 64 + mt * 16 + g;
            int col = wn * 32 + nt * 8 + t * 2;
            *reinterpret_cast<float2*>(&stage[row * 132 + col]) =
                make_float2(acc[mt][nt][0], acc[mt][nt][1]);
            *reinterpret_cast<float2*>(&stage[(row + 8) * 132 + col]) =
                make_float2(acc[mt][nt][2], acc[mt][nt][3]);
        }
    }
    __syncthreads();

#pragma unroll
    for (int i = 0; i < 16; i++) {
        int f   = i * 256 + tid;
        int row = f >> 5;
        int c4  = f & 31;
        float4 v = *reinterpret_cast<float4*>(&stage[row * 132 + c4 * 4]);
        if (BIAS) {
            float4 bv = *reinterpret_cast<const float4*>(bias + n0 + c4 * 4);
            v.x += bv.x; v.y += bv.y; v.z += bv.z; v.w += bv.w;
        }
        if (RELU) {
            v.x = fmaxf(v.x, 0.f); v.y = fmaxf(v.y, 0.f);
            v.z = fmaxf(v.z, 0.f); v.w = fmaxf(v.w, 0.f);
        }
        *reinterpret_cast<float4*>(C + (size_t)(m0 + row) * N + n0 + c4 * 4) = v;
    }
}

// ---------------------------------------------------------------------------
// Fused attention, fp32 — thread-per-q-row layout, ZERO warp shuffles.
// Block = 256 threads = 256 q rows of one (b,h). Keys stream via smem
// broadcast tiles of 32. Online softmax is per-thread scalar math.
// ---------------------------------------------------------------------------
template <bool CAUSAL>
__global__ void __launch_bounds__(256, 1)
attn_kernel(const float* __restrict__ Q, const float* __restrict__ K,
            const float* __restrict__ V, float* __restrict__ O, int Lk)
{
    __shared__ float Ks[32][64];
    __shared__ float Vs[32][64];

    const int b   = blockIdx.z;
    const int h   = blockIdx.y;
    const int q0  = blockIdx.x * 256;
    const int tid = threadIdx.x;
    const int row = q0 + tid;          // this thread's q row (within S)

    // q row into registers, pre-scaled by 1/sqrt(dh)
    float qr[64];
    {
        const float* qp = Q + (size_t)(b * Sc + row) * Dc + h * 64;
#pragma unroll
        for (int i = 0; i < 16; i++) {
            float4 v4 = *reinterpret_cast<const float4*>(qp + i * 4);
            qr[i * 4 + 0] = v4.x * 0.125f;
            qr[i * 4 + 1] = v4.y * 0.125f;
            qr[i * 4 + 2] = v4.z * 0.125f;
            qr[i * 4 + 3] = v4.w * 0.125f;
        }
    }
    float o[64];
#pragma unroll
    for (int d = 0; d < 64; d++) o[d] = 0.f;
    float m = -1e30f, l = 0.f;

    const int nkt = CAUSAL ? ((q0 + 256) >> 5) : (Lk >> 5);

    for (int kt = 0; kt < nkt; kt++) {
        const int k0 = kt << 5;
        __syncthreads();
        // cooperative tile load: 32 keys x 64 dims for K and V
#pragma unroll
        for (int i = 0; i < 2; i++) {
            int idx = tid + i * 256;       // 0..511
            int r   = idx >> 4;
            int c   = idx & 15;
            size_t base = (size_t)(b * Lk + k0 + r) * Dc + h * 64 + c * 4;
            *reinterpret_cast<float4*>(&Ks[r][c * 4]) =
                *reinterpret_cast<const float4*>(K + base);
            *reinterpret_cast<float4*>(&Vs[r][c * 4]) =
                *reinterpret_cast<const float4*>(V + base);
        }
        __syncthreads();
        if (CAUSAL && k0 > row) continue;   // tile fully masked for this row

        // scores (broadcast smem reads; no conflicts)
        float sc[32];
#pragma unroll 4
        for (int j = 0; j < 32; j++) {
            float s = 0.f;
#pragma unroll
            for (int d = 0; d < 64; d += 4) {
                float4 kv = *reinterpret_cast<const float4*>(&Ks[j][d]);
                s += qr[d] * kv.x + qr[d + 1] * kv.y + qr[d + 2] * kv.z + qr[d + 3] * kv.w;
            }
            sc[j] = (CAUSAL && (k0 + j) > row) ? -1e9f : s;
        }
        // per-thread online softmax (no shuffles)
        float mx = m;
#pragma unroll
        for (int j = 0; j < 32; j++) mx = fmaxf(mx, sc[j]);
        float alpha = __expf(m - mx);
        m = mx;
        l *= alpha;
#pragma unroll
        for (int d = 0; d < 64; d++) o[d] *= alpha;
#pragma unroll 4
        for (int j = 0; j < 32; j++) {
            float p = __expf(sc[j] - mx);
            l += p;
#pragma unroll
            for (int d = 0; d < 64; d += 4) {
                float4 vv = *reinterpret_cast<const float4*>(&Vs[j][d]);
                o[d]     += p * vv.x;
                o[d + 1] += p * vv.y;
                o[d + 2] += p * vv.z;
                o[d + 3] += p * vv.w;
            }
        }
    }

    const float inv = 1.f / l;
    float* op = O + (size_t)(b * Sc + row) * Dc + h * 64;
#pragma unroll
    for (int d = 0; d < 64; d += 4) {
        float4 v4 = make_float4(o[d] * inv, o[d + 1] * inv, o[d + 2] * inv, o[d + 3] * inv);
        *reinterpret_cast<float4*>(op + d) = v4;
    }
}

// ---------------------------------------------------------------------------
// Residual + LayerNorm
// ---------------------------------------------------------------------------
__global__ void __launch_bounds__(256)
ln_kernel(const float* __restrict__ x, const float* __restrict__ add,
          const float* __restrict__ s, const float* __restrict__ b,
          float* __restrict__ out)
{
    const int row = blockIdx.x;
    const int tid = threadIdx.x;
    const size_t base = (size_t)row * Dc;

    float v[4];
    float sum = 0.f, sq = 0.f;
#pragma unroll
    for (int i = 0; i < 4; i++) {
        int c = tid + i * 256;
        float val = x[base + c];
        if (add) val += add[base + c];
        v[i] = val;
        sum += val;
        sq  += val * val;
    }
#pragma unroll
    for (int off = 16; off > 0; off >>= 1) {
        sum += __shfl_xor_sync(0xffffffffu, sum, off);
        sq  += __shfl_xor_sync(0xffffffffu, sq, off);
    }
    __shared__ float s1[8], s2[8];
    __shared__ float mu_s, inv_s;
    int lane = tid & 31, wid = tid >> 5;
    if (lane == 0) { s1[wid] = sum; s2[wid] = sq; }
    __syncthreads();
    if (tid == 0) {
        float ts = 0.f, tq = 0.f;
#pragma unroll
        for (int i = 0; i < 8; i++) { ts += s1[i]; tq += s2[i]; }
        float mu  = ts * (1.f / Dc);
        float var = tq * (1.f / Dc) - mu * mu;
        mu_s  = mu;
        inv_s = rsqrtf(var + 1e-5f);
    }
    __syncthreads();
    float mu = mu_s, inv = inv_s;
#pragma unroll
    for (int i = 0; i < 4; i++) {
        int c = tid + i * 256;
        out[base + c] = (v[i] - mu) * inv * s[c] + b[c];
    }
}

// ---------------------------------------------------------------------------
// Embedding gather + positional add
// ---------------------------------------------------------------------------
__global__ void __launch_bounds__(256)
embed_kernel(const int* __restrict__ seq, const float* __restrict__ emb,
             const float* __restrict__ pos, float* __restrict__ x)
{
    const int row  = blockIdx.x;
    const int sidx = row & (Sc - 1);
    const int tok  = seq[row];
    const int tid  = threadIdx.x;
#pragma unroll
    for (int i = 0; i < 4; i++) {
        int c = tid + i * 256;
        x[(size_t)row * Dc + c] = emb[(size_t)tok * Dc + c] + pos[(size_t)sidx * Dc + c];
    }
}

// ---------------------------------------------------------------------------
// Host orchestration
// ---------------------------------------------------------------------------
template <bool BIAS, bool RELU>
static void launch_gemm(const float* A, const __nv_bfloat16* bhi, const __nv_bfloat16* blo,
                        const float* bias, float* C, int M, int N, int K)
{
    cudaFuncSetAttribute(tc_gemm<BIAS, RELU>,
                         cudaFuncAttributeMaxDynamicSharedMemorySize, GEMM_SMEM);
    dim3 grid(N / 128, M / 128);
    tc_gemm<BIAS, RELU><<<grid, 256, GEMM_SMEM>>>(A, bhi, blo, bias, C, M, N, K);
}

extern "C" void kernel_launch(void* const* d_in, const int* in_sizes, int n_in,
                              void* d_out, int out_size)
{
    (void)in_sizes; (void)n_in; (void)out_size;

    const float* encoded      = (const float*)d_in[0];
    const int*   seq          = (const int*)  d_in[1];
    const float* input_embed  = (const float*)d_in[2];
    const float* output_embed = (const float*)d_in[3];
    const float* output_bias  = (const float*)d_in[4];
    const float* pos_embed    = (const float*)d_in[5];
    const float* Wq  = (const float*)d_in[6];
    const float* Wk  = (const float*)d_in[7];
    const float* Wv  = (const float*)d_in[8];
    const float* Wo  = (const float*)d_in[9];
    const float* Wqc = (const float*)d_in[10];
    const float* Wkc = (const float*)d_in[11];
    const float* Wvc = (const float*)d_in[12];
    const float* Woc = (const float*)d_in[13];
    const float* W1  = (const float*)d_in[14];
    const float* b1  = (const float*)d_in[15];
    const float* W2  = (const float*)d_in[16];
    const float* b2  = (const float*)d_in[17];
    const float* ln1s = (const float*)d_in[18];
    const float* ln1b = (const float*)d_in[19];
    const float* ln2s = (const float*)d_in[20];
    const float* ln2b = (const float*)d_in[21];
    const float* ln3s = (const float*)d_in[22];
    const float* ln3b = (const float*)d_in[23];
    const float* lnfs = (const float*)d_in[24];
    const float* lnfb = (const float*)d_in[25];

    float *x, *q, *k, *v, *a, *o, *f;
    cudaGetSymbolAddress((void**)&x, g_x);
    cudaGetSymbolAddress((void**)&q, g_q);
    cudaGetSymbolAddress((void**)&k, g_k);
    cudaGetSymbolAddress((void**)&v, g_v);
    cudaGetSymbolAddress((void**)&a, g_a);
    cudaGetSymbolAddress((void**)&o, g_o);
    cudaGetSymbolAddress((void**)&f, g_f);
    __nv_bfloat16 *whi, *wlo;
    cudaGetSymbolAddress((void**)&whi, g_whi);
    cudaGetSymbolAddress((void**)&wlo, g_wlo);

    // ---- weight conversion: 4 launches ----
    const dim3 tb(32, 8);
    convT8_kernel<<<dim3(32, 32, Lc * 8), tb>>>(Wq, Wk, Wv, Wo, Wqc, Wkc, Wvc, Woc,
                                                whi, wlo);
    convT_kernel<<<dim3(DFc / 32, Dc / 32, Lc), tb>>>(
        W1, whi + WOFF_W1, wlo + WOFF_W1, Dc, DFc,
        (size_t)Dc * DFc, WOFF_LAYER);
    convT_kernel<<<dim3(Dc / 32, DFc / 32, Lc), tb>>>(
        W2, whi + WOFF_W2, wlo + WOFF_W2, DFc, Dc,
        (size_t)DFc * Dc, WOFF_LAYER);
    conv_kernel<<<Vc, 256>>>((const float4*)output_embed,
                             (__nv_bfloat162*)(whi + EOFF),
                             (__nv_bfloat162*)(wlo + EOFF));

    const int NR  = Bc * Sc;   // 4096
    const int NRE = Bc * Mc;   // 8192

    embed_kernel<<<NR, 256>>>(seq, input_embed, pos_embed, x);

    const dim3 agrid(Sc / 256, Hc, Bc);   // (2, 16, 8)

    for (int i = 0; i < Lc; i++) {
        const size_t lb = (size_t)i * WOFF_LAYER;
        const __nv_bfloat16* wq = whi + lb;
        const __nv_bfloat16* lq = wlo + lb;

        // ---- self attention ----
        launch_gemm<false, false>(x, wq + 0 * 1048576, lq + 0 * 1048576, nullptr, q, NR, Dc, Dc);
        launch_gemm<false, false>(x, wq + 1 * 1048576, lq + 1 * 1048576, nullptr, k, NR, Dc, Dc);
        launch_gemm<false, false>(x, wq + 2 * 1048576, lq + 2 * 1048576, nullptr, v, NR, Dc, Dc);
        attn_kernel<true><<<agrid, 256>>>(q, k, v, a, Sc);
        launch_gemm<false, false>(a, wq + 3 * 1048576, lq + 3 * 1048576, nullptr, o, NR, Dc, Dc);
        ln_kernel<<<NR, 256>>>(x, o, ln1s + (size_t)i * Dc, ln1b + (size_t)i * Dc, x);

        // ---- cross attention ----
        launch_gemm<false, false>(x,       wq + 4 * 1048576, lq + 4 * 1048576, nullptr, q, NR,  Dc, Dc);
        launch_gemm<false, false>(encoded, wq + 5 * 1048576, lq + 5 * 1048576, nullptr, k, NRE, Dc, Dc);
        launch_gemm<false, false>(encoded, wq + 6 * 1048576, lq + 6 * 1048576, nullptr, v, NRE, Dc, Dc);
        attn_kernel<false><<<agrid, 256>>>(q, k, v, a, Mc);
        launch_gemm<false, false>(a, wq + 7 * 1048576, lq + 7 * 1048576, nullptr, o, NR, Dc, Dc);
        ln_kernel<<<NR, 256>>>(x, o, ln2s + (size_t)i * Dc, ln2b + (size_t)i * Dc, x);

        // ---- FFN ----
        launch_gemm<true, true >(x, wq + WOFF_W1, lq + WOFF_W1, b1 + (size_t)i * DFc,
                                 f, NR, DFc, Dc);
        launch_gemm<true, false>(f, wq + WOFF_W2, lq + WOFF_W2, b2 + (size_t)i * Dc,
                                 o, NR, Dc, DFc);
        ln_kernel<<<NR, 256>>>(x, o, ln3s + (size_t)i * Dc, ln3b + (size_t)i * Dc, x);
    }

    // final norm + logits
    ln_kernel<<<NR, 256>>>(x, nullptr, lnfs, lnfb, x);
    launch_gemm<true, false>(x, whi + EOFF, wlo + EOFF, output_bias, (float*)d_out, NR, Vc, Dc);
}

// round 7
// speedup vs baseline: 1.0660x; 1.0660x over previous
#include <cuda_runtime.h>
#include <cuda_bf16.h>
#include <math.h>
#include <stdint.h>

// Problem constants
#define Bc   8
#define Sc   512
#define Dc   1024
#define Hc   16
#define DHc  64
#define Mc   1024
#define DFc  4096
#define Vc   32000
#define Lc   6

// ---------------------------------------------------------------------------
// Scratch (device globals)
// ---------------------------------------------------------------------------
__device__ float g_x[Bc * Sc * Dc];
__device__ float g_q[Bc * Sc * Dc];
__device__ float g_k[Bc * Mc * Dc];
__device__ float g_v[Bc * Mc * Dc];
__device__ float g_a[Bc * Sc * Dc];
__device__ float g_o[Bc * Sc * Dc];
__device__ float g_f[Bc * Sc * DFc];

// Pre-converted weights: [N,K] bf16 hi/lo.
#define WOFF_LAYER 16777216ull
#define WOFF_W1    8388608ull
#define WOFF_W2    12582912ull
#define EOFF       100663296ull
#define WTOTAL     133431296ull
__device__ __nv_bfloat16 g_whi[WTOTAL];
__device__ __nv_bfloat16 g_wlo[WTOTAL];

// ===========================================================================
// helpers
// ===========================================================================
__device__ __forceinline__ uint32_t smem_u32(const void* p) {
    uint32_t a;
    asm("{ .reg .u64 t; cvta.to.shared.u64 t, %1; cvt.u32.u64 %0, t; }"
        : "=r"(a) : "l"(p));
    return a;
}

__device__ __forceinline__ void split2(float x, float y, uint32_t& hi, uint32_t& lo) {
    __nv_bfloat162 h = __floats2bfloat162_rn(x, y);
    float rx = x - __low2float(h);
    float ry = y - __high2float(h);
    __nv_bfloat162 l = __floats2bfloat162_rn(rx, ry);
    hi = *reinterpret_cast<uint32_t*>(&h);
    lo = *reinterpret_cast<uint32_t*>(&l);
}

__device__ __forceinline__ void mma_bf16(float* d, const uint32_t* a, const uint32_t* b) {
    asm volatile(
        "mma.sync.aligned.m16n8k16.row.col.f32.bf16.bf16.f32 "
        "{%0,%1,%2,%3}, {%4,%5,%6,%7}, {%8,%9}, {%0,%1,%2,%3};"
        : "+f"(d[0]), "+f"(d[1]), "+f"(d[2]), "+f"(d[3])
        : "r"(a[0]), "r"(a[1]), "r"(a[2]), "r"(a[3]), "r"(b[0]), "r"(b[1]));
}

#define CP_ASYNC16(dst, src) \
    asm volatile("cp.async.cg.shared.global [%0], [%1], 16;" :: "r"(dst), "l"(src))
#define CP_COMMIT()  asm volatile("cp.async.commit_group;" ::: "memory")
#define CP_WAIT0()   asm volatile("cp.async.wait_group 0;" ::: "memory")

// ===========================================================================
// Weight conversion kernels (4 launches, batched)
// ===========================================================================
__global__ void convT8_kernel(const float* __restrict__ Wq, const float* __restrict__ Wk,
                              const float* __restrict__ Wv, const float* __restrict__ Wo,
                              const float* __restrict__ Wqc, const float* __restrict__ Wkc,
                              const float* __restrict__ Wvc, const float* __restrict__ Woc,
                              __nv_bfloat16* __restrict__ hi, __nv_bfloat16* __restrict__ lo)
{
    __shared__ float ts[32][33];
    const int z     = blockIdx.z;
    const int layer = z >> 3;
    const int j     = z & 7;
    const float* srcs[8] = { Wq, Wk, Wv, Wo, Wqc, Wkc, Wvc, Woc };
    const float* W = srcs[j] + (size_t)layer * Dc * Dc;
    __nv_bfloat16* ho  = hi + (size_t)layer * WOFF_LAYER + (size_t)j * 1048576;
    __nv_bfloat16* lo_ = lo + (size_t)layer * WOFF_LAYER + (size_t)j * 1048576;

    const int k0 = blockIdx.y * 32, n0 = blockIdx.x * 32;
    const int tx = threadIdx.x, ty = threadIdx.y;
#pragma unroll
    for (int jj = 0; jj < 4; jj++)
        ts[ty + jj * 8][tx] = W[(size_t)(k0 + ty + jj * 8) * Dc + n0 + tx];
    __syncthreads();
#pragma unroll
    for (int jj = 0; jj < 4; jj++) {
        int n = ty + jj * 8;
        float v = ts[tx][n];
        __nv_bfloat16 h = __float2bfloat16(v);
        float r = v - __bfloat162float(h);
        size_t o = (size_t)(n0 + n) * Dc + k0 + tx;
        ho[o]  = h;
        lo_[o] = __float2bfloat16(r);
    }
}

__global__ void convT_kernel(const float* __restrict__ W,
                             __nv_bfloat16* __restrict__ hi,
                             __nv_bfloat16* __restrict__ lo, int K, int N,
                             size_t srcStride, size_t dstStride)
{
    __shared__ float ts[32][33];
    const int z  = blockIdx.z;
    const float* Ws = W + (size_t)z * srcStride;
    __nv_bfloat16* ho  = hi + (size_t)z * dstStride;
    __nv_bfloat16* lo_ = lo + (size_t)z * dstStride;
    const int k0 = blockIdx.y * 32, n0 = blockIdx.x * 32;
    const int tx = threadIdx.x, ty = threadIdx.y;
#pragma unroll
    for (int j = 0; j < 4; j++)
        ts[ty + j * 8][tx] = Ws[(size_t)(k0 + ty + j * 8) * N + n0 + tx];
    __syncthreads();
#pragma unroll
    for (int j = 0; j < 4; j++) {
        int n = ty + j * 8;
        float v = ts[tx][n];
        __nv_bfloat16 h = __float2bfloat16(v);
        float r = v - __bfloat162float(h);
        size_t o = (size_t)(n0 + n) * K + k0 + tx;
        ho[o]  = h;
        lo_[o] = __float2bfloat16(r);
    }
}

__global__ void conv_kernel(const float4* __restrict__ src,
                            __nv_bfloat162* __restrict__ hi,
                            __nv_bfloat162* __restrict__ lo)
{
    size_t i = (size_t)blockIdx.x * blockDim.x + threadIdx.x;
    float4 v = src[i];
    __nv_bfloat162 h0 = __floats2bfloat162_rn(v.x, v.y);
    __nv_bfloat162 h1 = __floats2bfloat162_rn(v.z, v.w);
    float rx = v.x - __low2float(h0), ry = v.y - __high2float(h0);
    float rz = v.z - __low2float(h1), rw = v.w - __high2float(h1);
    hi[i * 2]     = h0;
    hi[i * 2 + 1] = h1;
    lo[i * 2]     = __floats2bfloat162_rn(rx, ry);
    lo[i * 2 + 1] = __floats2bfloat162_rn(rz, rw);
}

// ===========================================================================
// Tensor-core GEMM (R4-proven): C[M,N] = A[M,K](fp32) @ Wt[N,K](bf16 hi/lo)
// ===========================================================================
#define PITCH 72
#define TILEB (128 * PITCH * 2)
#define STAGEB (4 * TILEB)
#define GEMM_SMEM (2 * STAGEB)

template <bool BIAS, bool RELU>
__global__ void __launch_bounds__(256, 1)
tc_gemm(const float* __restrict__ A,
        const __nv_bfloat16* __restrict__ Bhi_g,
        const __nv_bfloat16* __restrict__ Blo_g,
        const float* __restrict__ bias, float* __restrict__ C,
        int M, int N, int K)
{
    extern __shared__ char smem[];
    const int tid  = threadIdx.x;
    const int wid  = tid >> 5;
    const int lane = tid & 31;
    const int g    = lane >> 2;
    const int t    = lane & 3;
    const int wm   = wid & 1;
    const int wn   = wid >> 1;
    const int m0   = blockIdx.y * 128;
    const int n0   = blockIdx.x * 128;

    const int arow = tid >> 4;
    const int ac4  = tid & 15;

    float4 aR[8];
    float acc[4][4][4];
#pragma unroll
    for (int i = 0; i < 4; i++)
#pragma unroll
        for (int j = 0; j < 4; j++)
#pragma unroll
            for (int c = 0; c < 4; c++) acc[i][j][c] = 0.f;

    const int S = K >> 6;

    auto ldgA = [&](int s) {
        const int k0 = s << 6;
#pragma unroll
        for (int i = 0; i < 8; i++) {
            int row = arow + i * 16;
            aR[i] = *reinterpret_cast<const float4*>(
                A + (size_t)(m0 + row) * K + k0 + ac4 * 4);
        }
    };

    auto stsA = [&](int b) {
        char* Ahi = smem + b * STAGEB;
        char* Alo = Ahi + TILEB;
#pragma unroll
        for (int i = 0; i < 8; i++) {
            int row = arow + i * 16;
            uint32_t h0, l0, h1, l1;
            split2(aR[i].x, aR[i].y, h0, l0);
            split2(aR[i].z, aR[i].w, h1, l1);
            uint32_t byte = (uint32_t)(row * (PITCH * 2) + ac4 * 8);
            *reinterpret_cast<uint64_t*>(Ahi + byte) = ((uint64_t)h1 << 32) | h0;
            *reinterpret_cast<uint64_t*>(Alo + byte) = ((uint64_t)l1 << 32) | l0;
        }
    };

    auto cpB = [&](int s, int b) {
        const int k0 = s << 6;
        char* Bhi_s = smem + b * STAGEB + 2 * TILEB;
        char* Blo_s = smem + b * STAGEB + 3 * TILEB;
#pragma unroll
        for (int i = 0; i < 8; i++) {
            int idx  = tid + i * 256;
            int r    = (idx & 1023) >> 3;
            int c16  = idx & 7;
            uint32_t dst;
            const __nv_bfloat16* src;
            if (i < 4) {
                src = Bhi_g + (size_t)(n0 + r) * K + k0 + c16 * 8;
                dst = smem_u32(Bhi_s + r * (PITCH * 2) + c16 * 16);
            } else {
                src = Blo_g + (size_t)(n0 + r) * K + k0 + c16 * 8;
                dst = smem_u32(Blo_s + r * (PITCH * 2) + c16 * 16);
            }
            CP_ASYNC16(dst, src);
        }
    };

    auto compute = [&](int b) {
        const __nv_bfloat16* Ah = reinterpret_cast<const __nv_bfloat16*>(smem + b * STAGEB);
        const __nv_bfloat16* Al = Ah + 128 * PITCH;
        const __nv_bfloat16* Bh = Al + 128 * PITCH;
        const __nv_bfloat16* Bl = Bh + 128 * PITCH;
#pragma unroll
        for (int ks = 0; ks < 4; ks++) {
            const int kb = ks * 16 + t * 2;
            uint32_t ah[4][4], al[4][4], bh[4][2], bl[4][2];
#pragma unroll
            for (int mt = 0; mt < 4; mt++) {
                const __nv_bfloat16* p = Ah + (wm * 64 + mt * 16 + g) * PITCH + kb;
                ah[mt][0] = *reinterpret_cast<const uint32_t*>(p);
                ah[mt][1] = *reinterpret_cast<const uint32_t*>(p + 8 * PITCH);
                ah[mt][2] = *reinterpret_cast<const uint32_t*>(p + 8);
                ah[mt][3] = *reinterpret_cast<const uint32_t*>(p + 8 * PITCH + 8);
            }
#pragma unroll
            for (int nt = 0; nt < 4; nt++) {
                const __nv_bfloat16* p = Bh + (wn * 32 + nt * 8 + g) * PITCH + kb;
                bh[nt][0] = *reinterpret_cast<const uint32_t*>(p);
                bh[nt][1] = *reinterpret_cast<const uint32_t*>(p + 8);
            }
#pragma unroll
            for (int mt = 0; mt < 4; mt++)
#pragma unroll
                for (int nt = 0; nt < 4; nt++)
                    mma_bf16(acc[mt][nt], ah[mt], bh[nt]);
#pragma unroll
            for (int nt = 0; nt < 4; nt++) {
                const __nv_bfloat16* p = Bl + (wn * 32 + nt * 8 + g) * PITCH + kb;
                bl[nt][0] = *reinterpret_cast<const uint32_t*>(p);
                bl[nt][1] = *reinterpret_cast<const uint32_t*>(p + 8);
            }
#pragma unroll
            for (int mt = 0; mt < 4; mt++)
#pragma unroll
                for (int nt = 0; nt < 4; nt++)
                    mma_bf16(acc[mt][nt], ah[mt], bl[nt]);
#pragma unroll
            for (int mt = 0; mt < 4; mt++) {
                const __nv_bfloat16* p = Al + (wm * 64 + mt * 16 + g) * PITCH + kb;
                al[mt][0] = *reinterpret_cast<const uint32_t*>(p);
                al[mt][1] = *reinterpret_cast<const uint32_t*>(p + 8 * PITCH);
                al[mt][2] = *reinterpret_cast<const uint32_t*>(p + 8);
                al[mt][3] = *reinterpret_cast<const uint32_t*>(p + 8 * PITCH + 8);
            }
#pragma unroll
            for (int mt = 0; mt < 4; mt++)
#pragma unroll
                for (int nt = 0; nt < 4; nt++)
                    mma_bf16(acc[mt][nt], al[mt], bh[nt]);
        }
    };

    ldgA(0);
    cpB(0, 0);
    CP_COMMIT();
    stsA(0);
    CP_WAIT0();
    __syncthreads();

    for (int s = 0; s < S; s++) {
        const int b = s & 1;
        if (s + 1 < S) { ldgA(s + 1); cpB(s + 1, b ^ 1); CP_COMMIT(); }
        compute(b);
        if (s + 1 < S) stsA(b ^ 1);
        CP_WAIT0();
        __syncthreads();
    }

    float* stage = reinterpret_cast<float*>(smem);
#pragma unroll
    for (int mt = 0; mt < 4; mt++) {
#pragma unroll
        for (int nt = 0; nt < 4; nt++) {
            int row = wm * 64 + mt * 16 + g;
            int col = wn * 32 + nt * 8 + t * 2;
            *reinterpret_cast<float2*>(&stage[row * 132 + col]) =
                make_float2(acc[mt][nt][0], acc[mt][nt][1]);
            *reinterpret_cast<float2*>(&stage[(row + 8) * 132 + col]) =
                make_float2(acc[mt][nt][2], acc[mt][nt][3]);
        }
    }
    __syncthreads();

#pragma unroll
    for (int i = 0; i < 16; i++) {
        int f   = i * 256 + tid;
        int row = f >> 5;
        int c4  = f & 31;
        float4 v = *reinterpret_cast<float4*>(&stage[row * 132 + c4 * 4]);
        if (BIAS) {
            float4 bv = *reinterpret_cast<const float4*>(bias + n0 + c4 * 4);
            v.x += bv.x; v.y += bv.y; v.z += bv.z; v.w += bv.w;
        }
        if (RELU) {
            v.x = fmaxf(v.x, 0.f); v.y = fmaxf(v.y, 0.f);
            v.z = fmaxf(v.z, 0.f); v.w = fmaxf(v.w, 0.f);
        }
        *reinterpret_cast<float4*>(C + (size_t)(m0 + row) * N + n0 + c4 * 4) = v;
    }
}

// ---------------------------------------------------------------------------
// Fused attention v3: 2 threads per q-row (adjacent lanes), each owns one
// 32-dim half of q and o. Score halves combined with ONE shfl_xor per key.
// Softmax max/sum: per-thread scalar (computed redundantly in both halves).
// Registers: qr[32] + o[32] + sc[32] ~ 130 — no spills.
// Block = 256 threads = 128 q rows.
// ---------------------------------------------------------------------------
template <bool CAUSAL>
__global__ void __launch_bounds__(256, 1)
attn_kernel(const float* __restrict__ Q, const float* __restrict__ K,
            const float* __restrict__ V, float* __restrict__ O, int Lk)
{
    __shared__ float Ks[32][64];
    __shared__ float Vs[32][64];

    const int b     = blockIdx.z;
    const int h     = blockIdx.y;
    const int q0    = blockIdx.x * 128;
    const int tid   = threadIdx.x;
    const int row   = q0 + (tid >> 1);
    const int dbase = (tid & 1) * 32;

    // half q row into registers, pre-scaled
    float qr[32];
    {
        const float* qp = Q + (size_t)(b * Sc + row) * Dc + h * 64 + dbase;
#pragma unroll
        for (int i = 0; i < 8; i++) {
            float4 v4 = *reinterpret_cast<const float4*>(qp + i * 4);
            qr[i * 4 + 0] = v4.x * 0.125f;
            qr[i * 4 + 1] = v4.y * 0.125f;
            qr[i * 4 + 2] = v4.z * 0.125f;
            qr[i * 4 + 3] = v4.w * 0.125f;
        }
    }
    float o[32];
#pragma unroll
    for (int d = 0; d < 32; d++) o[d] = 0.f;
    float m = -1e30f, l = 0.f;

    const int nkt = CAUSAL ? ((q0 + 128) >> 5) : (Lk >> 5);

    for (int kt = 0; kt < nkt; kt++) {
        const int k0 = kt << 5;
        __syncthreads();
#pragma unroll
        for (int i = 0; i < 2; i++) {
            int idx = tid + i * 256;
            int r   = idx >> 4;
            int c   = idx & 15;
            size_t base = (size_t)(b * Lk + k0 + r) * Dc + h * 64 + c * 4;
            *reinterpret_cast<float4*>(&Ks[r][c * 4]) =
                *reinterpret_cast<const float4*>(K + base);
            *reinterpret_cast<float4*>(&Vs[r][c * 4]) =
                *reinterpret_cast<const float4*>(V + base);
        }
        __syncthreads();
        if (CAUSAL && k0 > row) continue;

        // partial scores over this thread's 32 dims
        float sc[32];
#pragma unroll 4
        for (int j = 0; j < 32; j++) {
            const float* kp = &Ks[j][dbase];
            float s = 0.f;
#pragma unroll
            for (int d = 0; d < 32; d += 4) {
                float4 kv = *reinterpret_cast<const float4*>(kp + d);
                s += qr[d] * kv.x + qr[d + 1] * kv.y + qr[d + 2] * kv.z + qr[d + 3] * kv.w;
            }
            sc[j] = s;
        }
        // combine the two halves: one independent shuffle per key
#pragma unroll
        for (int j = 0; j < 32; j++)
            sc[j] += __shfl_xor_sync(0xffffffffu, sc[j], 1);
        if (CAUSAL) {
#pragma unroll
            for (int j = 0; j < 32; j++)
                if ((k0 + j) > row) sc[j] = -1e9f;
        }
        // per-thread online softmax (redundant across the pair; deterministic)
        float mx = m;
#pragma unroll
        for (int j = 0; j < 32; j++) mx = fmaxf(mx, sc[j]);
        float alpha = __expf(m - mx);
        m = mx;
        l *= alpha;
#pragma unroll
        for (int d = 0; d < 32; d++) o[d] *= alpha;
#pragma unroll 4
        for (int j = 0; j < 32; j++) {
            float p = __expf(sc[j] - mx);
            l += p;
            const float* vp = &Vs[j][dbase];
#pragma unroll
            for (int d = 0; d < 32; d += 4) {
                float4 vv = *reinterpret_cast<const float4*>(vp + d);
                o[d]     += p * vv.x;
                o[d + 1] += p * vv.y;
                o[d + 2] += p * vv.z;
                o[d + 3] += p * vv.w;
            }
        }
    }

    const float inv = 1.f / l;
    float* op = O + (size_t)(b * Sc + row) * Dc + h * 64 + dbase;
#pragma unroll
    for (int d = 0; d < 32; d += 4) {
        float4 v4 = make_float4(o[d] * inv, o[d + 1] * inv, o[d + 2] * inv, o[d + 3] * inv);
        *reinterpret_cast<float4*>(op + d) = v4;
    }
}

// ---------------------------------------------------------------------------
// Residual + LayerNorm
// ---------------------------------------------------------------------------
__global__ void __launch_bounds__(256)
ln_kernel(const float* __restrict__ x, const float* __restrict__ add,
          const float* __restrict__ s, const float* __restrict__ b,
          float* __restrict__ out)
{
    const int row = blockIdx.x;
    const int tid = threadIdx.x;
    const size_t base = (size_t)row * Dc;

    float v[4];
    float sum = 0.f, sq = 0.f;
#pragma unroll
    for (int i = 0; i < 4; i++) {
        int c = tid + i * 256;
        float val = x[base + c];
        if (add) val += add[base + c];
        v[i] = val;
        sum += val;
        sq  += val * val;
    }
#pragma unroll
    for (int off = 16; off > 0; off >>= 1) {
        sum += __shfl_xor_sync(0xffffffffu, sum, off);
        sq  += __shfl_xor_sync(0xffffffffu, sq, off);
    }
    __shared__ float s1[8], s2[8];
    __shared__ float mu_s, inv_s;
    int lane = tid & 31, wid = tid >> 5;
    if (lane == 0) { s1[wid] = sum; s2[wid] = sq; }
    __syncthreads();
    if (tid == 0) {
        float ts = 0.f, tq = 0.f;
#pragma unroll
        for (int i = 0; i < 8; i++) { ts += s1[i]; tq += s2[i]; }
        float mu  = ts * (1.f / Dc);
        float var = tq * (1.f / Dc) - mu * mu;
        mu_s  = mu;
        inv_s = rsqrtf(var + 1e-5f);
    }
    __syncthreads();
    float mu = mu_s, inv = inv_s;
#pragma unroll
    for (int i = 0; i < 4; i++) {
        int c = tid + i * 256;
        out[base + c] = (v[i] - mu) * inv * s[c] + b[c];
    }
}

// ---------------------------------------------------------------------------
// Embedding gather + positional add
// ---------------------------------------------------------------------------
__global__ void __launch_bounds__(256)
embed_kernel(const int* __restrict__ seq, const float* __restrict__ emb,
             const float* __restrict__ pos, float* __restrict__ x)
{
    const int row  = blockIdx.x;
    const int sidx = row & (Sc - 1);
    const int tok  = seq[row];
    const int tid  = threadIdx.x;
#pragma unroll
    for (int i = 0; i < 4; i++) {
        int c = tid + i * 256;
        x[(size_t)row * Dc + c] = emb[(size_t)tok * Dc + c] + pos[(size_t)sidx * Dc + c];
    }
}

// ---------------------------------------------------------------------------
// Host orchestration
// ---------------------------------------------------------------------------
template <bool BIAS, bool RELU>
static void launch_gemm(const float* A, const __nv_bfloat16* bhi, const __nv_bfloat16* blo,
                        const float* bias, float* C, int M, int N, int K)
{
    cudaFuncSetAttribute(tc_gemm<BIAS, RELU>,
                         cudaFuncAttributeMaxDynamicSharedMemorySize, GEMM_SMEM);
    dim3 grid(N / 128, M / 128);
    tc_gemm<BIAS, RELU><<<grid, 256, GEMM_SMEM>>>(A, bhi, blo, bias, C, M, N, K);
}

extern "C" void kernel_launch(void* const* d_in, const int* in_sizes, int n_in,
                              void* d_out, int out_size)
{
    (void)in_sizes; (void)n_in; (void)out_size;

    const float* encoded      = (const float*)d_in[0];
    const int*   seq          = (const int*)  d_in[1];
    const float* input_embed  = (const float*)d_in[2];
    const float* output_embed = (const float*)d_in[3];
    const float* output_bias  = (const float*)d_in[4];
    const float* pos_embed    = (const float*)d_in[5];
    const float* Wq  = (const float*)d_in[6];
    const float* Wk  = (const float*)d_in[7];
    const float* Wv  = (const float*)d_in[8];
    const float* Wo  = (const float*)d_in[9];
    const float* Wqc = (const float*)d_in[10];
    const float* Wkc = (const float*)d_in[11];
    const float* Wvc = (const float*)d_in[12];
    const float* Woc = (const float*)d_in[13];
    const float* W1  = (const float*)d_in[14];
    const float* b1  = (const float*)d_in[15];
    const float* W2  = (const float*)d_in[16];
    const float* b2  = (const float*)d_in[17];
    const float* ln1s = (const float*)d_in[18];
    const float* ln1b = (const float*)d_in[19];
    const float* ln2s = (const float*)d_in[20];
    const float* ln2b = (const float*)d_in[21];
    const float* ln3s = (const float*)d_in[22];
    const float* ln3b = (const float*)d_in[23];
    const float* lnfs = (const float*)d_in[24];
    const float* lnfb = (const float*)d_in[25];

    float *x, *q, *k, *v, *a, *o, *f;
    cudaGetSymbolAddress((void**)&x, g_x);
    cudaGetSymbolAddress((void**)&q, g_q);
    cudaGetSymbolAddress((void**)&k, g_k);
    cudaGetSymbolAddress((void**)&v, g_v);
    cudaGetSymbolAddress((void**)&a, g_a);
    cudaGetSymbolAddress((void**)&o, g_o);
    cudaGetSymbolAddress((void**)&f, g_f);
    __nv_bfloat16 *whi, *wlo;
    cudaGetSymbolAddress((void**)&whi, g_whi);
    cudaGetSymbolAddress((void**)&wlo, g_wlo);

    // ---- weight conversion: 4 launches ----
    const dim3 tb(32, 8);
    convT8_kernel<<<dim3(32, 32, Lc * 8), tb>>>(Wq, Wk, Wv, Wo, Wqc, Wkc, Wvc, Woc,
                                                whi, wlo);
    convT_kernel<<<dim3(DFc / 32, Dc / 32, Lc), tb>>>(
        W1, whi + WOFF_W1, wlo + WOFF_W1, Dc, DFc,
        (size_t)Dc * DFc, WOFF_LAYER);
    convT_kernel<<<dim3(Dc / 32, DFc / 32, Lc), tb>>>(
        W2, whi + WOFF_W2, wlo + WOFF_W2, DFc, Dc,
        (size_t)DFc * Dc, WOFF_LAYER);
    conv_kernel<<<Vc, 256>>>((const float4*)output_embed,
                             (__nv_bfloat162*)(whi + EOFF),
                             (__nv_bfloat162*)(wlo + EOFF));

    const int NR  = Bc * Sc;   // 4096
    const int NRE = Bc * Mc;   // 8192

    embed_kernel<<<NR, 256>>>(seq, input_embed, pos_embed, x);

    const dim3 agrid(Sc / 128, Hc, Bc);   // (4, 16, 8)

    for (int i = 0; i < Lc; i++) {
        const size_t lb = (size_t)i * WOFF_LAYER;
        const __nv_bfloat16* wq = whi + lb;
        const __nv_bfloat16* lq = wlo + lb;

        // ---- self attention ----
        launch_gemm<false, false>(x, wq + 0 * 1048576, lq + 0 * 1048576, nullptr, q, NR, Dc, Dc);
        launch_gemm<false, false>(x, wq + 1 * 1048576, lq + 1 * 1048576, nullptr, k, NR, Dc, Dc);
        launch_gemm<false, false>(x, wq + 2 * 1048576, lq + 2 * 1048576, nullptr, v, NR, Dc, Dc);
        attn_kernel<true><<<agrid, 256>>>(q, k, v, a, Sc);
        launch_gemm<false, false>(a, wq + 3 * 1048576, lq + 3 * 1048576, nullptr, o, NR, Dc, Dc);
        ln_kernel<<<NR, 256>>>(x, o, ln1s + (size_t)i * Dc, ln1b + (size_t)i * Dc, x);

        // ---- cross attention ----
        launch_gemm<false, false>(x,       wq + 4 * 1048576, lq + 4 * 1048576, nullptr, q, NR,  Dc, Dc);
        launch_gemm<false, false>(encoded, wq + 5 * 1048576, lq + 5 * 1048576, nullptr, k, NRE, Dc, Dc);
        launch_gemm<false, false>(encoded, wq + 6 * 1048576, lq + 6 * 1048576, nullptr, v, NRE, Dc, Dc);
        attn_kernel<false><<<agrid, 256>>>(q, k, v, a, Mc);
        launch_gemm<false, false>(a, wq + 7 * 1048576, lq + 7 * 1048576, nullptr, o, NR, Dc, Dc);
        ln_kernel<<<NR, 256>>>(x, o, ln2s + (size_t)i * Dc, ln2b + (size_t)i * Dc, x);

        // ---- FFN ----
        launch_gemm<true, true >(x, wq + WOFF_W1, lq + WOFF_W1, b1 + (size_t)i * DFc,
                                 f, NR, DFc, Dc);
        launch_gemm<true, false>(f, wq + WOFF_W2, lq + WOFF_W2, b2 + (size_t)i * Dc,
                                 o, NR, Dc, DFc);
        ln_kernel<<<NR, 256>>>(x, o, ln3s + (size_t)i * Dc, ln3b + (size_t)i * Dc, x);
    }

    // final norm + logits
    ln_kernel<<<NR, 256>>>(x, nullptr, lnfs, lnfb, x);
    launch_gemm<true, false>(x, whi + EOFF, wlo + EOFF, output_bias, (float*)d_out, NR, Vc, Dc);
}

// round 8
// speedup vs baseline: 1.3463x; 1.2630x over previous
#include <cuda_runtime.h>
#include <cuda_bf16.h>
#include <math.h>
#include <stdint.h>

// Problem constants
#define Bc   8
#define Sc   512
#define Dc   1024
#define Hc   16
#define DHc  64
#define Mc   1024
#define DFc  4096
#define Vc   32000
#define Lc   6

typedef __nv_bfloat16 bf16;

// ---------------------------------------------------------------------------
// Scratch (device globals)
// ---------------------------------------------------------------------------
__device__ float g_x[Bc * Sc * Dc];        // residual stream fp32
__device__ float g_q[Bc * Sc * Dc];
__device__ float g_k[Bc * Mc * Dc];
__device__ float g_v[Bc * Mc * Dc];
__device__ float g_o[Bc * Sc * Dc];
// hi/lo bf16 activation mirrors (GEMM A-side inputs)
__device__ bf16 g_xhi[Bc * Sc * Dc],  g_xlo[Bc * Sc * Dc];
__device__ bf16 g_ahi[Bc * Sc * Dc],  g_alo[Bc * Sc * Dc];
__device__ bf16 g_fhi[Bc * Sc * DFc], g_flo[Bc * Sc * DFc];
__device__ bf16 g_ehi[Bc * Mc * Dc],  g_elo[Bc * Mc * Dc];

// Pre-converted weights: [N,K] bf16 hi/lo.
#define WOFF_LAYER 16777216ull
#define WOFF_W1    8388608ull
#define WOFF_W2    12582912ull
#define EOFF       100663296ull
#define WTOTAL     133431296ull
__device__ bf16 g_whi[WTOTAL];
__device__ bf16 g_wlo[WTOTAL];

// ===========================================================================
// helpers
// ===========================================================================
__device__ __forceinline__ uint32_t smem_u32(const void* p) {
    uint32_t a;
    asm("{ .reg .u64 t; cvta.to.shared.u64 t, %1; cvt.u32.u64 %0, t; }"
        : "=r"(a) : "l"(p));
    return a;
}

__device__ __forceinline__ void mma_bf16(float* d, const uint32_t* a, const uint32_t* b) {
    asm volatile(
        "mma.sync.aligned.m16n8k16.row.col.f32.bf16.bf16.f32 "
        "{%0,%1,%2,%3}, {%4,%5,%6,%7}, {%8,%9}, {%0,%1,%2,%3};"
        : "+f"(d[0]), "+f"(d[1]), "+f"(d[2]), "+f"(d[3])
        : "r"(a[0]), "r"(a[1]), "r"(a[2]), "r"(a[3]), "r"(b[0]), "r"(b[1]));
}

#define CP_ASYNC16(dst, src) \
    asm volatile("cp.async.cg.shared.global [%0], [%1], 16;" :: "r"(dst), "l"(src))
#define CP_COMMIT()  asm volatile("cp.async.commit_group;" ::: "memory")
#define CP_WAIT1()   asm volatile("cp.async.wait_group 1;" ::: "memory")
#define CP_WAIT0()   asm volatile("cp.async.wait_group 0;" ::: "memory")

// split one float into hi/lo bf16
__device__ __forceinline__ void split1(float v, bf16& h, bf16& l) {
    h = __float2bfloat16(v);
    l = __float2bfloat16(v - __bfloat162float(h));
}

// ===========================================================================
// Weight / encoded conversion kernels
// ===========================================================================
__global__ void convT8_kernel(const float* __restrict__ Wq, const float* __restrict__ Wk,
                              const float* __restrict__ Wv, const float* __restrict__ Wo,
                              const float* __restrict__ Wqc, const float* __restrict__ Wkc,
                              const float* __restrict__ Wvc, const float* __restrict__ Woc,
                              bf16* __restrict__ hi, bf16* __restrict__ lo)
{
    __shared__ float ts[32][33];
    const int z     = blockIdx.z;
    const int layer = z >> 3;
    const int j     = z & 7;
    const float* srcs[8] = { Wq, Wk, Wv, Wo, Wqc, Wkc, Wvc, Woc };
    const float* W = srcs[j] + (size_t)layer * Dc * Dc;
    bf16* ho  = hi + (size_t)layer * WOFF_LAYER + (size_t)j * 1048576;
    bf16* lo_ = lo + (size_t)layer * WOFF_LAYER + (size_t)j * 1048576;

    const int k0 = blockIdx.y * 32, n0 = blockIdx.x * 32;
    const int tx = threadIdx.x, ty = threadIdx.y;
#pragma unroll
    for (int jj = 0; jj < 4; jj++)
        ts[ty + jj * 8][tx] = W[(size_t)(k0 + ty + jj * 8) * Dc + n0 + tx];
    __syncthreads();
#pragma unroll
    for (int jj = 0; jj < 4; jj++) {
        int n = ty + jj * 8;
        float v = ts[tx][n];
        size_t o = (size_t)(n0 + n) * Dc + k0 + tx;
        split1(v, ho[o], lo_[o]);
    }
}

__global__ void convT_kernel(const float* __restrict__ W,
                             bf16* __restrict__ hi, bf16* __restrict__ lo,
                             int K, int N, size_t srcStride, size_t dstStride)
{
    __shared__ float ts[32][33];
    const int z  = blockIdx.z;
    const float* Ws = W + (size_t)z * srcStride;
    bf16* ho  = hi + (size_t)z * dstStride;
    bf16* lo_ = lo + (size_t)z * dstStride;
    const int k0 = blockIdx.y * 32, n0 = blockIdx.x * 32;
    const int tx = threadIdx.x, ty = threadIdx.y;
#pragma unroll
    for (int j = 0; j < 4; j++)
        ts[ty + j * 8][tx] = Ws[(size_t)(k0 + ty + j * 8) * N + n0 + tx];
    __syncthreads();
#pragma unroll
    for (int j = 0; j < 4; j++) {
        int n = ty + j * 8;
        float v = ts[tx][n];
        size_t o = (size_t)(n0 + n) * K + k0 + tx;
        split1(v, ho[o], lo_[o]);
    }
}

__global__ void conv_kernel(const float4* __restrict__ src,
                            __nv_bfloat162* __restrict__ hi,
                            __nv_bfloat162* __restrict__ lo)
{
    size_t i = (size_t)blockIdx.x * blockDim.x + threadIdx.x;
    float4 v = src[i];
    __nv_bfloat162 h0 = __floats2bfloat162_rn(v.x, v.y);
    __nv_bfloat162 h1 = __floats2bfloat162_rn(v.z, v.w);
    float rx = v.x - __low2float(h0), ry = v.y - __high2float(h0);
    float rz = v.z - __low2float(h1), rw = v.w - __high2float(h1);
    hi[i * 2]     = h0;
    hi[i * 2 + 1] = h1;
    lo[i * 2]     = __floats2bfloat162_rn(rx, ry);
    lo[i * 2 + 1] = __floats2bfloat162_rn(rz, rw);
}

// ===========================================================================
// Tensor-core GEMM v2: all-bf16 operands via cp.async, 2 CTAs/SM.
//   C[M,N] = (Ahi+Alo)[M,K] @ (Bhi+Blo)[N,K]^T   (3-pass split, fp32 accum)
// 128x128 CTA tile, BK=32, 8 warps (2x4), warp tile 64x32.
// Smem: 2 logical rows packed per 144B physical row (conflict-free, 16B align).
// OUTSPLIT: write hi/lo bf16 instead of fp32 (for GEMM->GEMM chains).
// ===========================================================================
#define PROWB  144                        // physical row bytes (2 logical rows)
#define TILEB  (64 * PROWB)               // 9216 B per tile (128 logical rows)
#define STAGEB (4 * TILEB)                // 36864 B
#define GEMM_SMEM (2 * STAGEB)            // 73728 B

// logical row r (0..127) -> byte offset of its 64B payload
#define ROWOFF(r) (((r) & 63) * PROWB + ((r) >> 6) * 64)

template <bool BIAS, bool RELU, bool OUTSPLIT>
__global__ void __launch_bounds__(256, 2)
tc_gemm(const bf16* __restrict__ Ahi_g, const bf16* __restrict__ Alo_g,
        const bf16* __restrict__ Bhi_g, const bf16* __restrict__ Blo_g,
        const float* __restrict__ bias, float* __restrict__ C,
        bf16* __restrict__ Chi, bf16* __restrict__ Clo,
        int M, int N, int K)
{
    extern __shared__ char smem[];
    const int tid  = threadIdx.x;
    const int wid  = tid >> 5;
    const int lane = tid & 31;
    const int g    = lane >> 2;
    const int t    = lane & 3;
    const int wm   = wid & 1;
    const int wn   = wid >> 1;
    const int m0   = blockIdx.y * 128;
    const int n0   = blockIdx.x * 128;

    float acc[4][4][4];
#pragma unroll
    for (int i = 0; i < 4; i++)
#pragma unroll
        for (int j = 0; j < 4; j++)
#pragma unroll
            for (int c = 0; c < 4; c++) acc[i][j][c] = 0.f;

    const int S = K >> 5;

    // cp.async: 4 tensors x 512 chunks(16B) = 2048; 8 per thread.
    auto cp_stage = [&](int s, int b) {
        const int k0 = s << 5;
        char* base = smem + b * STAGEB;
#pragma unroll
        for (int i = 0; i < 8; i++) {
            const int sel  = i >> 1;                    // 0 Ahi,1 Alo,2 Bhi,3 Blo
            const int idx2 = tid + (i & 1) * 256;       // 0..511
            const int r    = idx2 >> 2;                 // 0..127
            const int c    = idx2 & 3;                  // 16B chunk
            const bf16* srcs[4] = { Ahi_g, Alo_g, Bhi_g, Blo_g };
            const int   rg  = (sel < 2 ? m0 : n0) + r;
            const bf16* src = srcs[sel] + (size_t)rg * K + k0 + c * 8;
            uint32_t dst = smem_u32(base + sel * TILEB + ROWOFF(r) + c * 16);
            CP_ASYNC16(dst, src);
        }
    };

    auto compute = [&](int b) {
        const char* base = smem + b * STAGEB;
        const char* Ah = base;
        const char* Al = base + TILEB;
        const char* Bh = base + 2 * TILEB;
        const char* Bl = base + 3 * TILEB;
        const int aoff = wm * 64;                 // half-select within phys row
        const int boff = (wn >> 1) * 64;
        const int brow = (wn & 1) * 32;
#pragma unroll
        for (int ks = 0; ks < 2; ks++) {
            const int kb = ks * 16 + t * 2;       // elem index; byte = kb*2
            uint32_t ah[4][4], al[4][4], bh[4][2], bl[4][2];
#pragma unroll
            for (int mt = 0; mt < 4; mt++) {
                const char* p = Ah + (mt * 16 + g) * PROWB + aoff + kb * 2;
                ah[mt][0] = *reinterpret_cast<const uint32_t*>(p);
                ah[mt][1] = *reinterpret_cast<const uint32_t*>(p + 8 * PROWB);
                ah[mt][2] = *reinterpret_cast<const uint32_t*>(p + 16);
                ah[mt][3] = *reinterpret_cast<const uint32_t*>(p + 8 * PROWB + 16);
            }
#pragma unroll
            for (int nt = 0; nt < 4; nt++) {
                const char* p = Bh + (brow + nt * 8 + g) * PROWB + boff + kb * 2;
                bh[nt][0] = *reinterpret_cast<const uint32_t*>(p);
                bh[nt][1] = *reinterpret_cast<const uint32_t*>(p + 16);
            }
#pragma unroll
            for (int mt = 0; mt < 4; mt++)
#pragma unroll
                for (int nt = 0; nt < 4; nt++)
                    mma_bf16(acc[mt][nt], ah[mt], bh[nt]);
#pragma unroll
            for (int nt = 0; nt < 4; nt++) {
                const char* p = Bl + (brow + nt * 8 + g) * PROWB + boff + kb * 2;
                bl[nt][0] = *reinterpret_cast<const uint32_t*>(p);
                bl[nt][1] = *reinterpret_cast<const uint32_t*>(p + 16);
            }
#pragma unroll
            for (int mt = 0; mt < 4; mt++)
#pragma unroll
                for (int nt = 0; nt < 4; nt++)
                    mma_bf16(acc[mt][nt], ah[mt], bl[nt]);
#pragma unroll
            for (int mt = 0; mt < 4; mt++) {
                const char* p = Al + (mt * 16 + g) * PROWB + aoff + kb * 2;
                al[mt][0] = *reinterpret_cast<const uint32_t*>(p);
                al[mt][1] = *reinterpret_cast<const uint32_t*>(p + 8 * PROWB);
                al[mt][2] = *reinterpret_cast<const uint32_t*>(p + 16);
                al[mt][3] = *reinterpret_cast<const uint32_t*>(p + 8 * PROWB + 16);
            }
#pragma unroll
            for (int mt = 0; mt < 4; mt++)
#pragma unroll
                for (int nt = 0; nt < 4; nt++)
                    mma_bf16(acc[mt][nt], al[mt], bh[nt]);
        }
    };

    // ---- pipeline: one stage in flight ----
    cp_stage(0, 0);
    CP_COMMIT();
    for (int s = 0; s < S; s++) {
        const int b = s & 1;
        if (s + 1 < S) { cp_stage(s + 1, b ^ 1); CP_COMMIT(); CP_WAIT1(); }
        else           { CP_WAIT0(); }
        __syncthreads();          // stage s visible to all
        compute(b);
        __syncthreads();          // all done with buffer b before it is refilled
    }

    // ---- epilogue: regs -> smem stage -> coalesced out ----
    float* stage = reinterpret_cast<float*>(smem);   // 128 x pitch 132 fp32
#pragma unroll
    for (int mt = 0; mt < 4; mt++) {
#pragma unroll
        for (int nt = 0; nt < 4; nt++) {
            int row = wm * 64 + mt * 16 + g;
            int col = wn * 32 + nt * 8 + t * 2;
            *reinterpret_cast<float2*>(&stage[row * 132 + col]) =
                make_float2(acc[mt][nt][0], acc[mt][nt][1]);
            *reinterpret_cast<float2*>(&stage[(row + 8) * 132 + col]) =
                make_float2(acc[mt][nt][2], acc[mt][nt][3]);
        }
    }
    __syncthreads();

#pragma unroll
    for (int i = 0; i < 16; i++) {
        int f   = i * 256 + tid;
        int row = f >> 5;
        int c4  = f & 31;
        float4 v = *reinterpret_cast<float4*>(&stage[row * 132 + c4 * 4]);
        if (BIAS) {
            float4 bv = *reinterpret_cast<const float4*>(bias + n0 + c4 * 4);
            v.x += bv.x; v.y += bv.y; v.z += bv.z; v.w += bv.w;
        }
        if (RELU) {
            v.x = fmaxf(v.x, 0.f); v.y = fmaxf(v.y, 0.f);
            v.z = fmaxf(v.z, 0.f); v.w = fmaxf(v.w, 0.f);
        }
        size_t oidx = (size_t)(m0 + row) * N + n0 + c4 * 4;
        if (OUTSPLIT) {
            __nv_bfloat162 h0 = __floats2bfloat162_rn(v.x, v.y);
            __nv_bfloat162 h1 = __floats2bfloat162_rn(v.z, v.w);
            float rx = v.x - __low2float(h0), ry = v.y - __high2float(h0);
            float rz = v.z - __low2float(h1), rw = v.w - __high2float(h1);
            *reinterpret_cast<__nv_bfloat162*>(Chi + oidx)     = h0;
            *reinterpret_cast<__nv_bfloat162*>(Chi + oidx + 2) = h1;
            *reinterpret_cast<__nv_bfloat162*>(Clo + oidx)     = __floats2bfloat162_rn(rx, ry);
            *reinterpret_cast<__nv_bfloat162*>(Clo + oidx + 2) = __floats2bfloat162_rn(rz, rw);
        } else {
            *reinterpret_cast<float4*>(C + oidx) = v;
        }
    }
}

// ---------------------------------------------------------------------------
// Fused attention (R4-proven layout: warp-per-8-rows, 128 threads, high occ).
// Output written directly as hi/lo bf16 (consumed by the o-projection GEMM).
// ---------------------------------------------------------------------------
template <bool CAUSAL>
__global__ void __launch_bounds__(128)
attn_kernel(const float* __restrict__ Q, const float* __restrict__ K,
            const float* __restrict__ V, bf16* __restrict__ Ohi,
            bf16* __restrict__ Olo, int Lk)
{
    __shared__ float Qs[32 * 64];
    __shared__ float Kst[64 * 33];
    __shared__ float Vs[32 * 68];
    __shared__ float Ps[32 * 32];

    const int b    = blockIdx.z;
    const int h    = blockIdx.y;
    const int q0   = blockIdx.x * 32;
    const int tid  = threadIdx.x;
    const int lane = tid & 31;
    const int w    = tid >> 5;
    const int r0   = w * 8;

#pragma unroll
    for (int s = tid; s < 512; s += 128) {
        int r  = s >> 4;
        int c4 = s & 15;
        float4 v = *reinterpret_cast<const float4*>(
            Q + (size_t)(b * Sc + q0 + r) * Dc + h * 64 + c4 * 4);
        *reinterpret_cast<float4*>(&Qs[r * 64 + c4 * 4]) = v;
    }

    float m_run[8], l_run[8], o0[8], o1[8];
#pragma unroll
    for (int r = 0; r < 8; r++) { m_run[r] = -1e30f; l_run[r] = 0.f; o0[r] = 0.f; o1[r] = 0.f; }

    const int nkt = CAUSAL ? (blockIdx.x + 1) : (Lk >> 5);

    for (int kt = 0; kt < nkt; kt++) {
        const int k0 = kt * 32;
        __syncthreads();
#pragma unroll
        for (int s = tid; s < 512; s += 128) {
            int r  = s >> 4;
            int c4 = s & 15;
            size_t base = (size_t)(b * Lk + k0 + r) * Dc + h * 64 + c4 * 4;
            float4 kv = *reinterpret_cast<const float4*>(K + base);
            Kst[(c4 * 4 + 0) * 33 + r] = kv.x;
            Kst[(c4 * 4 + 1) * 33 + r] = kv.y;
            Kst[(c4 * 4 + 2) * 33 + r] = kv.z;
            Kst[(c4 * 4 + 3) * 33 + r] = kv.w;
            float4 vv = *reinterpret_cast<const float4*>(V + base);
            *reinterpret_cast<float4*>(&Vs[r * 68 + c4 * 4]) = vv;
        }
        __syncthreads();

        float sc[8];
#pragma unroll
        for (int r = 0; r < 8; r++) sc[r] = 0.f;
#pragma unroll
        for (int d4 = 0; d4 < 16; d4++) {
            float k0v = Kst[(d4 * 4 + 0) * 33 + lane];
            float k1v = Kst[(d4 * 4 + 1) * 33 + lane];
            float k2v = Kst[(d4 * 4 + 2) * 33 + lane];
            float k3v = Kst[(d4 * 4 + 3) * 33 + lane];
#pragma unroll
            for (int r = 0; r < 8; r++) {
                float4 qv = *reinterpret_cast<const float4*>(&Qs[(r0 + r) * 64 + d4 * 4]);
                sc[r] += qv.x * k0v + qv.y * k1v + qv.z * k2v + qv.w * k3v;
            }
        }
#pragma unroll
        for (int r = 0; r < 8; r++) {
            sc[r] *= 0.125f;
            if (CAUSAL) {
                int qg = q0 + r0 + r;
                int kg = k0 + lane;
                if (kg > qg) sc[r] = -1e9f;
            }
        }
#pragma unroll
        for (int r = 0; r < 8; r++) {
            float mx = sc[r];
#pragma unroll
            for (int off = 16; off > 0; off >>= 1)
                mx = fmaxf(mx, __shfl_xor_sync(0xffffffffu, mx, off));
            float m_new = fmaxf(m_run[r], mx);
            float p = __expf(sc[r] - m_new);
            float ps = p;
#pragma unroll
            for (int off = 16; off > 0; off >>= 1)
                ps += __shfl_xor_sync(0xffffffffu, ps, off);
            float alpha = __expf(m_run[r] - m_new);
            l_run[r] = l_run[r] * alpha + ps;
            m_run[r] = m_new;
            o0[r] *= alpha;
            o1[r] *= alpha;
            Ps[(r0 + r) * 32 + lane] = p;
        }
        __syncwarp();
#pragma unroll
        for (int k4 = 0; k4 < 8; k4++) {
            float v00 = Vs[(k4 * 4 + 0) * 68 + lane];
            float v01 = Vs[(k4 * 4 + 1) * 68 + lane];
            float v02 = Vs[(k4 * 4 + 2) * 68 + lane];
            float v03 = Vs[(k4 * 4 + 3) * 68 + lane];
            float v10 = Vs[(k4 * 4 + 0) * 68 + 32 + lane];
            float v11 = Vs[(k4 * 4 + 1) * 68 + 32 + lane];
            float v12 = Vs[(k4 * 4 + 2) * 68 + 32 + lane];
            float v13 = Vs[(k4 * 4 + 3) * 68 + 32 + lane];
#pragma unroll
            for (int r = 0; r < 8; r++) {
                float4 pv = *reinterpret_cast<const float4*>(&Ps[(r0 + r) * 32 + k4 * 4]);
                o0[r] += pv.x * v00 + pv.y * v01 + pv.z * v02 + pv.w * v03;
                o1[r] += pv.x * v10 + pv.y * v11 + pv.z * v12 + pv.w * v13;
            }
        }
    }

#pragma unroll
    for (int r = 0; r < 8; r++) {
        float invl = 1.f / l_run[r];
        size_t base = (size_t)(b * Sc + q0 + r0 + r) * Dc + h * 64;
        float v0 = o0[r] * invl, v1 = o1[r] * invl;
        bf16 h0, l0, h1, l1;
        split1(v0, h0, l0);
        split1(v1, h1, l1);
        Ohi[base + lane]      = h0;
        Olo[base + lane]      = l0;
        Ohi[base + 32 + lane] = h1;
        Olo[base + 32 + lane] = l1;
    }
}

// ---------------------------------------------------------------------------
// Residual + LayerNorm; writes fp32 + hi/lo bf16 mirrors
// ---------------------------------------------------------------------------
__global__ void __launch_bounds__(256)
ln_kernel(const float* __restrict__ x, const float* __restrict__ add,
          const float* __restrict__ s, const float* __restrict__ b,
          float* __restrict__ out, bf16* __restrict__ ohi, bf16* __restrict__ olo)
{
    const int row = blockIdx.x;
    const int tid = threadIdx.x;
    const size_t base = (size_t)row * Dc;

    float v[4];
    float sum = 0.f, sq = 0.f;
#pragma unroll
    for (int i = 0; i < 4; i++) {
        int c = tid + i * 256;
        float val = x[base + c];
        if (add) val += add[base + c];
        v[i] = val;
        sum += val;
        sq  += val * val;
    }
#pragma unroll
    for (int off = 16; off > 0; off >>= 1) {
        sum += __shfl_xor_sync(0xffffffffu, sum, off);
        sq  += __shfl_xor_sync(0xffffffffu, sq, off);
    }
    __shared__ float s1[8], s2[8];
    __shared__ float mu_s, inv_s;
    int lane = tid & 31, wid = tid >> 5;
    if (lane == 0) { s1[wid] = sum; s2[wid] = sq; }
    __syncthreads();
    if (tid == 0) {
        float ts = 0.f, tq = 0.f;
#pragma unroll
        for (int i = 0; i < 8; i++) { ts += s1[i]; tq += s2[i]; }
        float mu  = ts * (1.f / Dc);
        float var = tq * (1.f / Dc) - mu * mu;
        mu_s  = mu;
        inv_s = rsqrtf(var + 1e-5f);
    }
    __syncthreads();
    float mu = mu_s, inv = inv_s;
#pragma unroll
    for (int i = 0; i < 4; i++) {
        int c = tid + i * 256;
        float r = (v[i] - mu) * inv * s[c] + b[c];
        out[base + c] = r;
        bf16 h, l;
        split1(r, h, l);
        ohi[base + c] = h;
        olo[base + c] = l;
    }
}

// ---------------------------------------------------------------------------
// Embedding gather + positional add; writes fp32 + hi/lo
// ---------------------------------------------------------------------------
__global__ void __launch_bounds__(256)
embed_kernel(const int* __restrict__ seq, const float* __restrict__ emb,
             const float* __restrict__ pos, float* __restrict__ x,
             bf16* __restrict__ xhi, bf16* __restrict__ xlo)
{
    const int row  = blockIdx.x;
    const int sidx = row & (Sc - 1);
    const int tok  = seq[row];
    const int tid  = threadIdx.x;
#pragma unroll
    for (int i = 0; i < 4; i++) {
        int c = tid + i * 256;
        float r = emb[(size_t)tok * Dc + c] + pos[(size_t)sidx * Dc + c];
        size_t o = (size_t)row * Dc + c;
        x[o] = r;
        bf16 h, l;
        split1(r, h, l);
        xhi[o] = h;
        xlo[o] = l;
    }
}

// ---------------------------------------------------------------------------
// Host orchestration
// ---------------------------------------------------------------------------
template <bool BIAS, bool RELU, bool OUTSPLIT>
static void launch_gemm(const bf16* ahi, const bf16* alo,
                        const bf16* bhi, const bf16* blo,
                        const float* bias, float* C, bf16* chi, bf16* clo,
                        int M, int N, int K)
{
    cudaFuncSetAttribute(tc_gemm<BIAS, RELU, OUTSPLIT>,
                         cudaFuncAttributeMaxDynamicSharedMemorySize, GEMM_SMEM);
    dim3 grid(N / 128, M / 128);
    tc_gemm<BIAS, RELU, OUTSPLIT><<<grid, 256, GEMM_SMEM>>>(
        ahi, alo, bhi, blo, bias, C, chi, clo, M, N, K);
}

extern "C" void kernel_launch(void* const* d_in, const int* in_sizes, int n_in,
                              void* d_out, int out_size)
{
    (void)in_sizes; (void)n_in; (void)out_size;

    const float* encoded      = (const float*)d_in[0];
    const int*   seq          = (const int*)  d_in[1];
    const float* input_embed  = (const float*)d_in[2];
    const float* output_embed = (const float*)d_in[3];
    const float* output_bias  = (const float*)d_in[4];
    const float* pos_embed    = (const float*)d_in[5];
    const float* Wq  = (const float*)d_in[6];
    const float* Wk  = (const float*)d_in[7];
    const float* Wv  = (const float*)d_in[8];
    const float* Wo  = (const float*)d_in[9];
    const float* Wqc = (const float*)d_in[10];
    const float* Wkc = (const float*)d_in[11];
    const float* Wvc = (const float*)d_in[12];
    const float* Woc = (const float*)d_in[13];
    const float* W1  = (const float*)d_in[14];
    const float* b1  = (const float*)d_in[15];
    const float* W2  = (const float*)d_in[16];
    const float* b2  = (const float*)d_in[17];
    const float* ln1s = (const float*)d_in[18];
    const float* ln1b = (const float*)d_in[19];
    const float* ln2s = (const float*)d_in[20];
    const float* ln2b = (const float*)d_in[21];
    const float* ln3s = (const float*)d_in[22];
    const float* ln3b = (const float*)d_in[23];
    const float* lnfs = (const float*)d_in[24];
    const float* lnfb = (const float*)d_in[25];

    float *x, *q, *k, *v, *o;
    cudaGetSymbolAddress((void**)&x, g_x);
    cudaGetSymbolAddress((void**)&q, g_q);
    cudaGetSymbolAddress((void**)&k, g_k);
    cudaGetSymbolAddress((void**)&v, g_v);
    cudaGetSymbolAddress((void**)&o, g_o);
    bf16 *whi, *wlo, *xhi, *xlo, *ahi, *alo, *fhi, *flo, *ehi, *elo;
    cudaGetSymbolAddress((void**)&whi, g_whi);
    cudaGetSymbolAddress((void**)&wlo, g_wlo);
    cudaGetSymbolAddress((void**)&xhi, g_xhi);
    cudaGetSymbolAddress((void**)&xlo, g_xlo);
    cudaGetSymbolAddress((void**)&ahi, g_ahi);
    cudaGetSymbolAddress((void**)&alo, g_alo);
    cudaGetSymbolAddress((void**)&fhi, g_fhi);
    cudaGetSymbolAddress((void**)&flo, g_flo);
    cudaGetSymbolAddress((void**)&ehi, g_ehi);
    cudaGetSymbolAddress((void**)&elo, g_elo);

    // ---- weight + encoded conversion: 5 launches ----
    const dim3 tb(32, 8);
    convT8_kernel<<<dim3(32, 32, Lc * 8), tb>>>(Wq, Wk, Wv, Wo, Wqc, Wkc, Wvc, Woc,
                                                whi, wlo);
    convT_kernel<<<dim3(DFc / 32, Dc / 32, Lc), tb>>>(
        W1, whi + WOFF_W1, wlo + WOFF_W1, Dc, DFc,
        (size_t)Dc * DFc, WOFF_LAYER);
    convT_kernel<<<dim3(Dc / 32, DFc / 32, Lc), tb>>>(
        W2, whi + WOFF_W2, wlo + WOFF_W2, DFc, Dc,
        (size_t)DFc * Dc, WOFF_LAYER);
    conv_kernel<<<Vc, 256>>>((const float4*)output_embed,
                             (__nv_bfloat162*)(whi + EOFF),
                             (__nv_bfloat162*)(wlo + EOFF));
    conv_kernel<<<Bc * Mc, 256>>>((const float4*)encoded,
                                  (__nv_bfloat162*)ehi, (__nv_bfloat162*)elo);

    const int NR  = Bc * Sc;   // 4096
    const int NRE = Bc * Mc;   // 8192

    embed_kernel<<<NR, 256>>>(seq, input_embed, pos_embed, x, xhi, xlo);

    const dim3 agrid(Sc / 32, Hc, Bc);   // (16, 16, 8)

    for (int i = 0; i < Lc; i++) {
        const size_t lb = (size_t)i * WOFF_LAYER;
        const bf16* wq = whi + lb;
        const bf16* lq = wlo + lb;

        // ---- self attention ----
        launch_gemm<false, false, false>(xhi, xlo, wq + 0 * 1048576, lq + 0 * 1048576,
                                         nullptr, q, nullptr, nullptr, NR, Dc, Dc);
        launch_gemm<false, false, false>(xhi, xlo, wq + 1 * 1048576, lq + 1 * 1048576,
                                         nullptr, k, nullptr, nullptr, NR, Dc, Dc);
        launch_gemm<false, false, false>(xhi, xlo, wq + 2 * 1048576, lq + 2 * 1048576,
                                         nullptr, v, nullptr, nullptr, NR, Dc, Dc);
        attn_kernel<true><<<agrid, 128>>>(q, k, v, ahi, alo, Sc);
        launch_gemm<false, false, false>(ahi, alo, wq + 3 * 1048576, lq + 3 * 1048576,
                                         nullptr, o, nullptr, nullptr, NR, Dc, Dc);
        ln_kernel<<<NR, 256>>>(x, o, ln1s + (size_t)i * Dc, ln1b + (size_t)i * Dc,
                               x, xhi, xlo);

        // ---- cross attention ----
        launch_gemm<false, false, false>(xhi, xlo, wq + 4 * 1048576, lq + 4 * 1048576,
                                         nullptr, q, nullptr, nullptr, NR, Dc, Dc);
        launch_gemm<false, false, false>(ehi, elo, wq + 5 * 1048576, lq + 5 * 1048576,
                                         nullptr, k, nullptr, nullptr, NRE, Dc, Dc);
        launch_gemm<false, false, false>(ehi, elo, wq + 6 * 1048576, lq + 6 * 1048576,
                                         nullptr, v, nullptr, nullptr, NRE, Dc, Dc);
        attn_kernel<false><<<agrid, 128>>>(q, k, v, ahi, alo, Mc);
        launch_gemm<false, false, false>(ahi, alo, wq + 7 * 1048576, lq + 7 * 1048576,
                                         nullptr, o, nullptr, nullptr, NR, Dc, Dc);
        ln_kernel<<<NR, 256>>>(x, o, ln2s + (size_t)i * Dc, ln2b + (size_t)i * Dc,
                               x, xhi, xlo);

        // ---- FFN ----
        launch_gemm<true, true, true>(xhi, xlo, wq + WOFF_W1, lq + WOFF_W1,
                                      b1 + (size_t)i * DFc, nullptr, fhi, flo,
                                      NR, DFc, Dc);
        launch_gemm<true, false, false>(fhi, flo, wq + WOFF_W2, lq + WOFF_W2,
                                        b2 + (size_t)i * Dc, o, nullptr, nullptr,
                                        NR, Dc, DFc);
        ln_kernel<<<NR, 256>>>(x, o, ln3s + (size_t)i * Dc, ln3b + (size_t)i * Dc,
                               x, xhi, xlo);
    }

    // final norm + logits
    ln_kernel<<<NR, 256>>>(x, nullptr, lnfs, lnfb, x, xhi, xlo);
    launch_gemm<true, false, false>(xhi, xlo, whi + EOFF, wlo + EOFF,
                                    output_bias, (float*)d_out, nullptr, nullptr,
                                    NR, Vc, Dc);
}